// round 8
// baseline (speedup 1.0000x reference)
#include <cuda_runtime.h>
#include <cuda_bf16.h>
#include <stdint.h>

#define NB 2
#define TT 8
#define NN 4096
#define FF 32
#define OO 32
#define CC 256   // T*F columns of the diffusion GEMMs

// GEMM tiling: block 128x64, 8 warps of 32x32, BK=64 (128B rows)
#define BM 128
#define BN 64
#define BK 64
#define STAGES 4
#define A_BYTES (BM * 128)           // 16384
#define B_BYTES (BN * 128)           // 8192
#define STAGE_BYTES (A_BYTES + B_BYTES)            // 24576
#define SMEM_TOTAL (STAGES * STAGE_BYTES)          // 98304

// Scratch (static device globals; no allocation in kernel_launch)
__device__ __nv_bfloat16 g_Abf[(size_t)NB * NN * NN];  // A in bf16
__device__ __nv_bfloat16 g_Xt[(size_t)NB * CC * NN];   // [b][c=t*32+f][m], bf16
__device__ __nv_bfloat16 g_Ybf[(size_t)NB * CC * NN];  // Y transposed, bf16
__device__ __nv_bfloat16 g_Wbf[(size_t)NB * CC * NN];  // W transposed, bf16

// ---------------------------------------------------------------------------
// Helpers
// ---------------------------------------------------------------------------
__device__ __forceinline__ uint32_t smem_u32(const void* p) {
    return (uint32_t)__cvta_generic_to_shared(p);
}
__device__ __forceinline__ void ldm4(uint32_t* r, uint32_t addr) {
    asm volatile("ldmatrix.sync.aligned.m8n8.x4.shared.b16 {%0,%1,%2,%3}, [%4];\n"
                 : "=r"(r[0]), "=r"(r[1]), "=r"(r[2]), "=r"(r[3]) : "r"(addr));
}
__device__ __forceinline__ void mma16816(float* d, const uint32_t* a, const uint32_t* b) {
    asm volatile(
        "mma.sync.aligned.m16n8k16.row.col.f32.bf16.bf16.f32 "
        "{%0,%1,%2,%3}, {%4,%5,%6,%7}, {%8,%9}, {%0,%1,%2,%3};\n"
        : "+f"(d[0]), "+f"(d[1]), "+f"(d[2]), "+f"(d[3])
        : "r"(a[0]), "r"(a[1]), "r"(a[2]), "r"(a[3]), "r"(b[0]), "r"(b[1]));
}
#define CP16(dst, src) \
    asm volatile("cp.async.cg.shared.global [%0], [%1], 16;\n" :: "r"(dst), "l"(src))
#define CP_COMMIT() asm volatile("cp.async.commit_group;\n" ::)
#define CP_WAIT2()  asm volatile("cp.async.wait_group 2;\n" ::)

// ---------------------------------------------------------------------------
// A fp32 -> bf16
// ---------------------------------------------------------------------------
__global__ __launch_bounds__(256) void conv_A(const float* __restrict__ A) {
    size_t idx = ((size_t)blockIdx.x * 256 + threadIdx.x) * 8;
    float4 v0 = *(const float4*)(A + idx);
    float4 v1 = *(const float4*)(A + idx + 4);
    uint4 o;
    __nv_bfloat162 p;
    p = __floats2bfloat162_rn(v0.x, v0.y); o.x = *(uint32_t*)&p;
    p = __floats2bfloat162_rn(v0.z, v0.w); o.y = *(uint32_t*)&p;
    p = __floats2bfloat162_rn(v1.x, v1.y); o.z = *(uint32_t*)&p;
    p = __floats2bfloat162_rn(v1.z, v1.w); o.w = *(uint32_t*)&p;
    *(uint4*)(g_Abf + idx) = o;
}

// ---------------------------------------------------------------------------
// Prep: Xt[b][t*32+f][m] = bf16(X[b][t][m][f])  (32x32 tiled transpose)
// ---------------------------------------------------------------------------
__global__ __launch_bounds__(256) void prep_xt(const float* __restrict__ X) {
    int bid = blockIdx.x;
    int mt = bid & 127;
    int bt = bid >> 7;
    int b = bt >> 3, t = bt & 7;
    __shared__ float s[32][33];
    const float* src = X + ((size_t)bt * NN + (size_t)mt * 32) * FF;
    for (int idx = threadIdx.x; idx < 1024; idx += 256) {
        int i = idx >> 5, f = idx & 31;
        s[i][f] = src[i * FF + f];
    }
    __syncthreads();
    __nv_bfloat16* dst = g_Xt + ((size_t)b * CC + t * FF) * NN + (size_t)mt * 32;
    for (int idx = threadIdx.x; idx < 1024; idx += 256) {
        int f = idx >> 5, i = idx & 31;
        dst[(size_t)f * NN + i] = __float2bfloat16(s[i][f]);
    }
}

// ---------------------------------------------------------------------------
// GEMM: D[c][n] = sum_m A[b][n][m] * Bt[b][c][m]  (M=4096, C=256, K=4096)
// 256 threads, 8 warps of 32x32 (4M x 2N). bf16 cp.async 4-stage pipeline,
// BK=64, one barrier per chunk, mma.sync m16n8k16. XOR-swizzled 128B rows.
// ---------------------------------------------------------------------------
template <int PASS>
__global__ __launch_bounds__(256) void gemm_diffuse() {
    extern __shared__ __align__(1024) char smem[];
    const uint32_t sb = smem_u32(smem);

    const int b  = blockIdx.z;
    const int n0 = blockIdx.y * BM;
    const int c0 = blockIdx.x * BN;
    const __nv_bfloat16* Ag = g_Abf + (size_t)b * NN * NN + (size_t)n0 * NN;
    const __nv_bfloat16* Bg = (PASS == 1 ? g_Xt : g_Ybf) + (size_t)b * CC * NN + (size_t)c0 * NN;

    const int tid  = threadIdx.x;
    const int lane = tid & 31;
    const int warp = tid >> 5;
    const int wm = (warp >> 1) * 32;  // warp M offset (0/32/64/96)
    const int wn = (warp & 1) * 32;   // warp N offset (0/32)

    // Load geometry: row = tid>>3 (+32i), 16B chunk = tid&7 within 128B row.
    const int lrow = tid >> 3;           // 0..31
    const int lck  = (tid & 7) * 16;
    const size_t kel = (size_t)(tid & 7) * 8;

    float acc[2][4][4];
#pragma unroll
    for (int i = 0; i < 2; i++)
#pragma unroll
        for (int j = 0; j < 4; j++)
#pragma unroll
            for (int d = 0; d < 4; d++) acc[i][j][d] = 0.f;

    auto issue = [&](int ch, int stg) {
        uint32_t base = sb + (uint32_t)stg * STAGE_BYTES;
        size_t k0 = (size_t)ch * BK + kel;
#pragma unroll
        for (int i = 0; i < 4; i++) {
            int row = lrow + i * 32;
            uint32_t off = ((uint32_t)row * 128 + lck) ^ ((row & 7) << 4);
            CP16(base + off, Ag + (size_t)row * NN + k0);
        }
#pragma unroll
        for (int i = 0; i < 2; i++) {
            int row = lrow + i * 32;
            uint32_t off = ((uint32_t)row * 128 + lck) ^ ((row & 7) << 4);
            CP16(base + A_BYTES + off, Bg + (size_t)row * NN + k0);
        }
    };

    issue(0, 0); CP_COMMIT();
    issue(1, 1); CP_COMMIT();
    issue(2, 2); CP_COMMIT();

    // Per-lane fragment geometry
    const int aRow = wm + (lane & 15);                      // + mi*16
    const uint32_t aColX = ((lane >> 4) << 4);
    const int bRow = wn + (lane & 7) + ((lane >> 4) << 3);  // + ni*16
    const uint32_t bColX = (((lane >> 3) & 1) << 4);

    const int NCH = NN / BK;  // 64
    for (int ch = 0; ch < NCH; ch++) {
        CP_WAIT2();
        __syncthreads();
        int j = ch + 3;
        if (j < NCH) issue(j, j & 3);   // stage consumed at iteration ch-1
        CP_COMMIT();

        uint32_t aB = sb + (uint32_t)(ch & 3) * STAGE_BYTES;
        uint32_t bB = aB + A_BYTES;
#pragma unroll
        for (int kk = 0; kk < 4; kk++) {         // 4 k16 steps within BK=64
            uint32_t kb = kk * 32;
            uint32_t afr[2][4], bfr[2][4];
#pragma unroll
            for (int ni = 0; ni < 2; ni++) {
                int row = bRow + ni * 16;
                uint32_t off = ((uint32_t)row * 128 + kb + bColX) ^ ((row & 7) << 4);
                ldm4(bfr[ni], bB + off);
            }
#pragma unroll
            for (int mi = 0; mi < 2; mi++) {
                int row = aRow + mi * 16;
                uint32_t off = ((uint32_t)row * 128 + kb + aColX) ^ ((row & 7) << 4);
                ldm4(afr[mi], aB + off);
            }
#pragma unroll
            for (int mi = 0; mi < 2; mi++)
#pragma unroll
                for (int nj = 0; nj < 4; nj++)
                    mma16816(acc[mi][nj], afr[mi], &bfr[nj >> 1][(nj & 1) * 2]);
        }
    }

    // Epilogue: write bf16 transposed [c][n]
    __nv_bfloat16* Og = (PASS == 1 ? g_Ybf : g_Wbf) + (size_t)b * CC * NN;
    int r0 = lane >> 2;
    int cq = (lane & 3) * 2;
#pragma unroll
    for (int mi = 0; mi < 2; mi++) {
#pragma unroll
        for (int nj = 0; nj < 4; nj++) {
#pragma unroll
            for (int d = 0; d < 4; d++) {
                int row = n0 + wm + mi * 16 + r0 + ((d >> 1) << 3);
                int col = c0 + wn + nj * 8 + cq + (d & 1);
                Og[(size_t)col * NN + row] = __float2bfloat16(acc[mi][nj][d]);
            }
        }
    }
}

// ---------------------------------------------------------------------------
// Finalize: out[b,t,n,o] = relu( X·(θ0-θ2) + Y·θ1 + 2W·θ2 + bias )
// Coefs hoisted to registers; X/Y/W in [n][36] rows, float4 broadcast loads.
// ---------------------------------------------------------------------------
__global__ __launch_bounds__(256) void finalize(const float* __restrict__ X,
                                                const float* __restrict__ Th,
                                                const float* __restrict__ bias,
                                                float* __restrict__ out) {
    __shared__ float C0[32][32], C1[32][32], C2[32][32];
    __shared__ float sbias[32];
    __shared__ float Xs[64][36];   // row stride 144B (16B aligned)
    __shared__ float Ys[64][36];
    __shared__ float Ws[64][36];

    int b = blockIdx.z, t = blockIdx.y, n0 = blockIdx.x * 64;
    int tid = threadIdx.x;

    for (int i = tid; i < 1024; i += 256) {
        int f = i >> 5, o = i & 31;
        float t2 = Th[(3 * f + 2) * 32 + o];
        C0[f][o] = Th[(3 * f + 0) * 32 + o] - t2;
        C1[f][o] = Th[(3 * f + 1) * 32 + o];
        C2[f][o] = 2.f * t2;
    }
    if (tid < 32) sbias[tid] = bias[tid];

    const float* Xp = X + (((size_t)b * TT + t) * NN + n0) * FF;
    for (int i = tid; i < 64 * 32; i += 256) {
        int n = i >> 5, f = i & 31;
        Xs[n][f] = Xp[n * FF + f];
    }
    const __nv_bfloat16* Yp = g_Ybf + ((size_t)b * CC + t * FF) * NN + n0;
    const __nv_bfloat16* Wp = g_Wbf + ((size_t)b * CC + t * FF) * NN + n0;
    for (int i = tid; i < 32 * 64; i += 256) {
        int f = i >> 6, n = i & 63;
        Ys[n][f] = __bfloat162float(Yp[(size_t)f * NN + n]);
        Ws[n][f] = __bfloat162float(Wp[(size_t)f * NN + n]);
    }
    __syncthreads();

    int warp = tid >> 5, lane = tid & 31;

    // Hoist coefficients for this thread's output column into registers
    float c0r[32], c1r[32], c2r[32];
#pragma unroll
    for (int f = 0; f < 32; f++) {
        c0r[f] = C0[f][lane];
        c1r[f] = C1[f][lane];
        c2r[f] = C2[f][lane];
    }

    float acc[8];
#pragma unroll
    for (int j = 0; j < 8; j++) acc[j] = sbias[lane];

#pragma unroll
    for (int f4 = 0; f4 < 8; f4++) {
#pragma unroll
        for (int j = 0; j < 8; j++) {
            int n = warp * 8 + j;
            float4 xv = *(const float4*)&Xs[n][f4 * 4];
            float4 yv = *(const float4*)&Ys[n][f4 * 4];
            float4 wv = *(const float4*)&Ws[n][f4 * 4];
            float a = acc[j];
            a = fmaf(xv.x, c0r[f4 * 4 + 0], a);
            a = fmaf(yv.x, c1r[f4 * 4 + 0], a);
            a = fmaf(wv.x, c2r[f4 * 4 + 0], a);
            a = fmaf(xv.y, c0r[f4 * 4 + 1], a);
            a = fmaf(yv.y, c1r[f4 * 4 + 1], a);
            a = fmaf(wv.y, c2r[f4 * 4 + 1], a);
            a = fmaf(xv.z, c0r[f4 * 4 + 2], a);
            a = fmaf(yv.z, c1r[f4 * 4 + 2], a);
            a = fmaf(wv.z, c2r[f4 * 4 + 2], a);
            a = fmaf(xv.w, c0r[f4 * 4 + 3], a);
            a = fmaf(yv.w, c1r[f4 * 4 + 3], a);
            a = fmaf(wv.w, c2r[f4 * 4 + 3], a);
            acc[j] = a;
        }
    }

    float* op = out + (((size_t)b * TT + t) * NN + n0) * OO;
#pragma unroll
    for (int j = 0; j < 8; j++) {
        int n = warp * 8 + j;
        op[n * OO + lane] = fmaxf(acc[j], 0.f);
    }
}

// ---------------------------------------------------------------------------
extern "C" void kernel_launch(void* const* d_in, const int* in_sizes, int n_in,
                              void* d_out, int out_size) {
    const float* X    = (const float*)d_in[0];
    const float* A    = (const float*)d_in[1];
    const float* Th   = (const float*)d_in[2];
    const float* bias = (const float*)d_in[3];
    float* out = (float*)d_out;

    cudaFuncSetAttribute(gemm_diffuse<1>, cudaFuncAttributeMaxDynamicSharedMemorySize, SMEM_TOTAL);
    cudaFuncSetAttribute(gemm_diffuse<2>, cudaFuncAttributeMaxDynamicSharedMemorySize, SMEM_TOTAL);

    conv_A<<<(NB * NN * NN) / (256 * 8), 256>>>(A);
    prep_xt<<<NB * TT * 128, 256>>>(X);

    dim3 gg(CC / BN, NN / BM, NB);                   // (4, 32, 2) = 256 blocks
    gemm_diffuse<1><<<gg, 256, SMEM_TOTAL>>>();      // Y = A * X
    gemm_diffuse<2><<<gg, 256, SMEM_TOTAL>>>();      // W = A * Y

    dim3 gf(NN / 64, TT, NB);                        // 1024 blocks
    finalize<<<gf, 256>>>(X, Th, bias, out);
}

// round 11
// speedup vs baseline: 1.0486x; 1.0486x over previous
#include <cuda_runtime.h>
#include <cuda_bf16.h>
#include <stdint.h>

#define NB 2
#define TT 8
#define NN 4096
#define FF 32
#define OO 32
#define CC 256   // T*F columns of the diffusion GEMMs

// GEMM tiling: block 128x64, 4 warps of 64x32, BK=64 (128B rows)
#define BM 128
#define BN 64
#define BK 64
#define STAGES 4
#define A_BYTES (BM * 128)           // 16384
#define B_BYTES (BN * 128)           // 8192
#define STAGE_BYTES (A_BYTES + B_BYTES)            // 24576
#define SMEM_TOTAL (STAGES * STAGE_BYTES)          // 98304

// Scratch (static device globals; no allocation in kernel_launch)
__device__ __nv_bfloat16 g_Abf[(size_t)NB * NN * NN];  // A in bf16
__device__ __nv_bfloat16 g_Xt[(size_t)NB * CC * NN];   // [b][c=t*32+f][m], bf16
__device__ __nv_bfloat16 g_Ybf[(size_t)NB * CC * NN];  // Y transposed, bf16
__device__ __nv_bfloat16 g_Wbf[(size_t)NB * CC * NN];  // W transposed, bf16

// ---------------------------------------------------------------------------
// Helpers
// ---------------------------------------------------------------------------
__device__ __forceinline__ uint32_t smem_u32(const void* p) {
    return (uint32_t)__cvta_generic_to_shared(p);
}
__device__ __forceinline__ void ldm4(uint32_t* r, uint32_t addr) {
    asm volatile("ldmatrix.sync.aligned.m8n8.x4.shared.b16 {%0,%1,%2,%3}, [%4];\n"
                 : "=r"(r[0]), "=r"(r[1]), "=r"(r[2]), "=r"(r[3]) : "r"(addr));
}
__device__ __forceinline__ void mma16816(float* d, const uint32_t* a, const uint32_t* b) {
    asm volatile(
        "mma.sync.aligned.m16n8k16.row.col.f32.bf16.bf16.f32 "
        "{%0,%1,%2,%3}, {%4,%5,%6,%7}, {%8,%9}, {%0,%1,%2,%3};\n"
        : "+f"(d[0]), "+f"(d[1]), "+f"(d[2]), "+f"(d[3])
        : "r"(a[0]), "r"(a[1]), "r"(a[2]), "r"(a[3]), "r"(b[0]), "r"(b[1]));
}
#define CP16(dst, src) \
    asm volatile("cp.async.cg.shared.global [%0], [%1], 16;\n" :: "r"(dst), "l"(src))
#define CP_COMMIT() asm volatile("cp.async.commit_group;\n" ::)
#define CP_WAIT2()  asm volatile("cp.async.wait_group 2;\n" ::)

// ---------------------------------------------------------------------------
// A fp32 -> bf16
// ---------------------------------------------------------------------------
__global__ __launch_bounds__(256) void conv_A(const float* __restrict__ A) {
    size_t idx = ((size_t)blockIdx.x * 256 + threadIdx.x) * 8;
    float4 v0 = *(const float4*)(A + idx);
    float4 v1 = *(const float4*)(A + idx + 4);
    uint4 o;
    __nv_bfloat162 p;
    p = __floats2bfloat162_rn(v0.x, v0.y); o.x = *(uint32_t*)&p;
    p = __floats2bfloat162_rn(v0.z, v0.w); o.y = *(uint32_t*)&p;
    p = __floats2bfloat162_rn(v1.x, v1.y); o.z = *(uint32_t*)&p;
    p = __floats2bfloat162_rn(v1.z, v1.w); o.w = *(uint32_t*)&p;
    *(uint4*)(g_Abf + idx) = o;
}

// ---------------------------------------------------------------------------
// Prep: Xt[b][t*32+f][m] = bf16(X[b][t][m][f])  (32x32 tiled transpose)
// ---------------------------------------------------------------------------
__global__ __launch_bounds__(256) void prep_xt(const float* __restrict__ X) {
    int bid = blockIdx.x;
    int mt = bid & 127;
    int bt = bid >> 7;
    int b = bt >> 3, t = bt & 7;
    __shared__ float s[32][33];
    const float* src = X + ((size_t)bt * NN + (size_t)mt * 32) * FF;
    for (int idx = threadIdx.x; idx < 1024; idx += 256) {
        int i = idx >> 5, f = idx & 31;
        s[i][f] = src[i * FF + f];
    }
    __syncthreads();
    __nv_bfloat16* dst = g_Xt + ((size_t)b * CC + t * FF) * NN + (size_t)mt * 32;
    for (int idx = threadIdx.x; idx < 1024; idx += 256) {
        int f = idx >> 5, i = idx & 31;
        dst[(size_t)f * NN + i] = __float2bfloat16(s[i][f]);
    }
}

// ---------------------------------------------------------------------------
// GEMM: D[c][n] = sum_m A[b][n][m] * Bt[b][c][m]  (M=4096, C=256, K=4096)
// 128 threads, 4 warps of 64x32. bf16 cp.async 4-stage pipeline, BK=64,
// one barrier per chunk, mma.sync m16n8k16. Fragment double-buffering with
// manually staged kk steps; cp.async issue overlapped with first prefetch.
// ---------------------------------------------------------------------------
template <int PASS>
__global__ __launch_bounds__(128) void gemm_diffuse() {
    extern __shared__ __align__(1024) char smem[];
    const uint32_t sb = smem_u32(smem);

    const int b  = blockIdx.z;
    const int n0 = blockIdx.y * BM;
    const int c0 = blockIdx.x * BN;
    const __nv_bfloat16* Ag = g_Abf + (size_t)b * NN * NN + (size_t)n0 * NN;
    const __nv_bfloat16* Bg = (PASS == 1 ? g_Xt : g_Ybf) + (size_t)b * CC * NN + (size_t)c0 * NN;

    const int tid  = threadIdx.x;
    const int lane = tid & 31;
    const int warp = tid >> 5;
    const int wm = (warp >> 1) * 64;  // warp M offset (0 / 64)
    const int wn = (warp & 1) * 32;   // warp N offset (0 / 32)

    // Load geometry: row = tid>>3 (+16i), 16B chunk = tid&7 within 128B row.
    const int lrow = tid >> 3;           // 0..15
    const int lck  = (tid & 7) * 16;
    const size_t kel = (size_t)(tid & 7) * 8;

    float acc[4][4][4];
#pragma unroll
    for (int i = 0; i < 4; i++)
#pragma unroll
        for (int j = 0; j < 4; j++)
#pragma unroll
            for (int d = 0; d < 4; d++) acc[i][j][d] = 0.f;

    auto issue = [&](int ch, int stg) {
        uint32_t base = sb + (uint32_t)stg * STAGE_BYTES;
        size_t k0 = (size_t)ch * BK + kel;
#pragma unroll
        for (int i = 0; i < 8; i++) {
            int row = lrow + i * 16;
            uint32_t off = ((uint32_t)row * 128 + lck) ^ ((row & 7) << 4);
            CP16(base + off, Ag + (size_t)row * NN + k0);
        }
#pragma unroll
        for (int i = 0; i < 4; i++) {
            int row = lrow + i * 16;
            uint32_t off = ((uint32_t)row * 128 + lck) ^ ((row & 7) << 4);
            CP16(base + A_BYTES + off, Bg + (size_t)row * NN + k0);
        }
    };

    issue(0, 0); CP_COMMIT();
    issue(1, 1); CP_COMMIT();
    issue(2, 2); CP_COMMIT();

    // Per-lane fragment geometry
    const int aRow = wm + (lane & 15);                      // + mi*16
    const uint32_t aColX = ((lane >> 4) << 4);
    const int bRow = wn + (lane & 7) + ((lane >> 4) << 3);  // + ni*16
    const uint32_t bColX = (((lane >> 3) & 1) << 4);

    uint32_t afr0[4][4], afr1[4][4], bfr0[2][4], bfr1[2][4];

    // Fragment fetch for one k16 step (kb = byte col base) into given buffers.
    auto fetchB = [&](uint32_t kb, uint32_t (*bf)[4]) {
#pragma unroll
        for (int ni = 0; ni < 2; ni++) {
            int row = bRow + ni * 16;
            uint32_t off = ((uint32_t)row * 128 + kb + bColX) ^ ((row & 7) << 4);
            ldm4(bf[ni], sb + 0 /*patched by caller base*/ + off);
        }
    };
    (void)fetchB;  // not used; explicit below for clarity

    const int NCH = NN / BK;  // 64
    for (int ch = 0; ch < NCH; ch++) {
        CP_WAIT2();
        __syncthreads();

        uint32_t aB = sb + (uint32_t)(ch & 3) * STAGE_BYTES;
        uint32_t bB = aB + A_BYTES;

        // Prefetch kk=0 fragments into buffer 0
#pragma unroll
        for (int ni = 0; ni < 2; ni++) {
            int row = bRow + ni * 16;
            uint32_t off = ((uint32_t)row * 128 + bColX) ^ ((row & 7) << 4);
            ldm4(bfr0[ni], bB + off);
        }
#pragma unroll
        for (int mi = 0; mi < 4; mi++) {
            int row = aRow + mi * 16;
            uint32_t off = ((uint32_t)row * 128 + aColX) ^ ((row & 7) << 4);
            ldm4(afr0[mi], aB + off);
        }

        // Issue next smem stage while kk=0 fragments are in flight
        int j = ch + 3;
        if (j < NCH) issue(j, j & 3);   // stage consumed at iteration ch-1
        CP_COMMIT();

        // kk=0 MMAs (buf0) interleaved with kk=1 prefetch (buf1)
#pragma unroll
        for (int ni = 0; ni < 2; ni++) {
            int row = bRow + ni * 16;
            uint32_t off = ((uint32_t)row * 128 + 32 + bColX) ^ ((row & 7) << 4);
            ldm4(bfr1[ni], bB + off);
        }
#pragma unroll
        for (int mi = 0; mi < 4; mi++) {
            int row = aRow + mi * 16;
            uint32_t off = ((uint32_t)row * 128 + 32 + aColX) ^ ((row & 7) << 4);
            ldm4(afr1[mi], aB + off);
        }
#pragma unroll
        for (int mi = 0; mi < 4; mi++)
#pragma unroll
            for (int nj = 0; nj < 4; nj++)
                mma16816(acc[mi][nj], afr0[mi], &bfr0[nj >> 1][(nj & 1) * 2]);

        // kk=1 MMAs (buf1), prefetch kk=2 (buf0)
#pragma unroll
        for (int ni = 0; ni < 2; ni++) {
            int row = bRow + ni * 16;
            uint32_t off = ((uint32_t)row * 128 + 64 + bColX) ^ ((row & 7) << 4);
            ldm4(bfr0[ni], bB + off);
        }
#pragma unroll
        for (int mi = 0; mi < 4; mi++) {
            int row = aRow + mi * 16;
            uint32_t off = ((uint32_t)row * 128 + 64 + aColX) ^ ((row & 7) << 4);
            ldm4(afr0[mi], aB + off);
        }
#pragma unroll
        for (int mi = 0; mi < 4; mi++)
#pragma unroll
            for (int nj = 0; nj < 4; nj++)
                mma16816(acc[mi][nj], afr1[mi], &bfr1[nj >> 1][(nj & 1) * 2]);

        // kk=2 MMAs (buf0), prefetch kk=3 (buf1)
#pragma unroll
        for (int ni = 0; ni < 2; ni++) {
            int row = bRow + ni * 16;
            uint32_t off = ((uint32_t)row * 128 + 96 + bColX) ^ ((row & 7) << 4);
            ldm4(bfr1[ni], bB + off);
        }
#pragma unroll
        for (int mi = 0; mi < 4; mi++) {
            int row = aRow + mi * 16;
            uint32_t off = ((uint32_t)row * 128 + 96 + aColX) ^ ((row & 7) << 4);
            ldm4(afr1[mi], aB + off);
        }
#pragma unroll
        for (int mi = 0; mi < 4; mi++)
#pragma unroll
            for (int nj = 0; nj < 4; nj++)
                mma16816(acc[mi][nj], afr0[mi], &bfr0[nj >> 1][(nj & 1) * 2]);

        // kk=3 MMAs (buf1)
#pragma unroll
        for (int mi = 0; mi < 4; mi++)
#pragma unroll
            for (int nj = 0; nj < 4; nj++)
                mma16816(acc[mi][nj], afr1[mi], &bfr1[nj >> 1][(nj & 1) * 2]);
    }

    // Epilogue: write bf16 transposed [c][n]
    __nv_bfloat16* Og = (PASS == 1 ? g_Ybf : g_Wbf) + (size_t)b * CC * NN;
    int r0 = lane >> 2;
    int cq = (lane & 3) * 2;
#pragma unroll
    for (int mi = 0; mi < 4; mi++) {
#pragma unroll
        for (int nj = 0; nj < 4; nj++) {
#pragma unroll
            for (int d = 0; d < 4; d++) {
                int row = n0 + wm + mi * 16 + r0 + ((d >> 1) << 3);
                int col = c0 + wn + nj * 8 + cq + (d & 1);
                Og[(size_t)col * NN + row] = __float2bfloat16(acc[mi][nj][d]);
            }
        }
    }
}

// ---------------------------------------------------------------------------
// Finalize: out[b,t,n,o] = relu( X·(θ0-θ2) + Y·θ1 + 2W·θ2 + bias )
// Coefs hoisted to registers; X/Y/W in [n][36] rows, float4 broadcast loads.
// ---------------------------------------------------------------------------
__global__ __launch_bounds__(256) void finalize(const float* __restrict__ X,
                                                const float* __restrict__ Th,
                                                const float* __restrict__ bias,
                                                float* __restrict__ out) {
    __shared__ float C0[32][32], C1[32][32], C2[32][32];
    __shared__ float sbias[32];
    __shared__ float Xs[64][36];   // row stride 144B (16B aligned)
    __shared__ float Ys[64][36];
    __shared__ float Ws[64][36];

    int b = blockIdx.z, t = blockIdx.y, n0 = blockIdx.x * 64;
    int tid = threadIdx.x;

    for (int i = tid; i < 1024; i += 256) {
        int f = i >> 5, o = i & 31;
        float t2 = Th[(3 * f + 2) * 32 + o];
        C0[f][o] = Th[(3 * f + 0) * 32 + o] - t2;
        C1[f][o] = Th[(3 * f + 1) * 32 + o];
        C2[f][o] = 2.f * t2;
    }
    if (tid < 32) sbias[tid] = bias[tid];

    const float* Xp = X + (((size_t)b * TT + t) * NN + n0) * FF;
    for (int i = tid; i < 64 * 32; i += 256) {
        int n = i >> 5, f = i & 31;
        Xs[n][f] = Xp[n * FF + f];
    }
    const __nv_bfloat16* Yp = g_Ybf + ((size_t)b * CC + t * FF) * NN + n0;
    const __nv_bfloat16* Wp = g_Wbf + ((size_t)b * CC + t * FF) * NN + n0;
    for (int i = tid; i < 32 * 64; i += 256) {
        int f = i >> 6, n = i & 63;
        Ys[n][f] = __bfloat162float(Yp[(size_t)f * NN + n]);
        Ws[n][f] = __bfloat162float(Wp[(size_t)f * NN + n]);
    }
    __syncthreads();

    int warp = tid >> 5, lane = tid & 31;

    float c0r[32], c1r[32], c2r[32];
#pragma unroll
    for (int f = 0; f < 32; f++) {
        c0r[f] = C0[f][lane];
        c1r[f] = C1[f][lane];
        c2r[f] = C2[f][lane];
    }

    float acc[8];
#pragma unroll
    for (int j = 0; j < 8; j++) acc[j] = sbias[lane];

#pragma unroll
    for (int f4 = 0; f4 < 8; f4++) {
#pragma unroll
        for (int j = 0; j < 8; j++) {
            int n = warp * 8 + j;
            float4 xv = *(const float4*)&Xs[n][f4 * 4];
            float4 yv = *(const float4*)&Ys[n][f4 * 4];
            float4 wv = *(const float4*)&Ws[n][f4 * 4];
            float a = acc[j];
            a = fmaf(xv.x, c0r[f4 * 4 + 0], a);
            a = fmaf(yv.x, c1r[f4 * 4 + 0], a);
            a = fmaf(wv.x, c2r[f4 * 4 + 0], a);
            a = fmaf(xv.y, c0r[f4 * 4 + 1], a);
            a = fmaf(yv.y, c1r[f4 * 4 + 1], a);
            a = fmaf(wv.y, c2r[f4 * 4 + 1], a);
            a = fmaf(xv.z, c0r[f4 * 4 + 2], a);
            a = fmaf(yv.z, c1r[f4 * 4 + 2], a);
            a = fmaf(wv.z, c2r[f4 * 4 + 2], a);
            a = fmaf(xv.w, c0r[f4 * 4 + 3], a);
            a = fmaf(yv.w, c1r[f4 * 4 + 3], a);
            a = fmaf(wv.w, c2r[f4 * 4 + 3], a);
            acc[j] = a;
        }
    }

    float* op = out + (((size_t)b * TT + t) * NN + n0) * OO;
#pragma unroll
    for (int j = 0; j < 8; j++) {
        int n = warp * 8 + j;
        op[n * OO + lane] = fmaxf(acc[j], 0.f);
    }
}

// ---------------------------------------------------------------------------
extern "C" void kernel_launch(void* const* d_in, const int* in_sizes, int n_in,
                              void* d_out, int out_size) {
    const float* X    = (const float*)d_in[0];
    const float* A    = (const float*)d_in[1];
    const float* Th   = (const float*)d_in[2];
    const float* bias = (const float*)d_in[3];
    float* out = (float*)d_out;

    cudaFuncSetAttribute(gemm_diffuse<1>, cudaFuncAttributeMaxDynamicSharedMemorySize, SMEM_TOTAL);
    cudaFuncSetAttribute(gemm_diffuse<2>, cudaFuncAttributeMaxDynamicSharedMemorySize, SMEM_TOTAL);

    conv_A<<<(NB * NN * NN) / (256 * 8), 256>>>(A);
    prep_xt<<<NB * TT * 128, 256>>>(X);

    dim3 gg(CC / BN, NN / BM, NB);                   // (4, 32, 2) = 256 blocks
    gemm_diffuse<1><<<gg, 128, SMEM_TOTAL>>>();      // Y = A * X
    gemm_diffuse<2><<<gg, 128, SMEM_TOTAL>>>();      // W = A * Y

    dim3 gf(NN / 64, TT, NB);                        // 1024 blocks
    finalize<<<gf, 256>>>(X, Th, bias, out);
}